// round 10
// baseline (speedup 1.0000x reference)
#include <cuda_runtime.h>
#include <cuda_bf16.h>

#define T_STEPS 64
#define BATCH   256
#define NI      2048
#define NH      4096
#define NO      128
#define BN      (BATCH * NH)      // 1048576
#define BO      (BATCH * NO)      // 32768

// ---------------- persistent device scratch (static: no runtime allocs) ----------------
__device__ float g_cur1[(size_t)T_STEPS * BN];   // 256 MiB: precomputed layer-1 currents
__device__ float g_mem1[BN];
__device__ float g_spk1[BN];
__device__ float g_mem2[BO];
__device__ float g_W2T[NH * NO];                 // W2 transposed: [k][o], 2 MiB

// ---------------- packed f32x2 helpers (per-lane IEEE rn rounding) ---------------------
__device__ __forceinline__ void ffma2(unsigned long long &d, unsigned long long a,
                                      unsigned long long b) {
    asm("fma.rn.f32x2 %0, %1, %2, %0;" : "+l"(d) : "l"(a), "l"(b));
}
__device__ __forceinline__ void fadd2(unsigned long long &d, unsigned long long a) {
    asm("add.rn.f32x2 %0, %0, %1;" : "+l"(d) : "l"(a));
}
__device__ __forceinline__ unsigned long long dup2(float x) {
    unsigned long long r;
    asm("mov.b64 %0, {%1, %1};" : "=l"(r) : "f"(x));
    return r;
}
__device__ __forceinline__ float2 unp(unsigned long long v) {
    float2 r;
    asm("mov.b64 {%0, %1}, %2;" : "=f"(r.x), "=f"(r.y) : "l"(v));
    return r;
}

// ---------------- init: zero recurrent state + transpose W2 ---------------------------
__global__ void init_kernel(const float* __restrict__ W2) {
    int i = blockIdx.x * blockDim.x + threadIdx.x;
    if (i < BN) g_mem1[i] = 0.0f;
    if (i < BO) g_mem2[i] = 0.0f;
    if (i < NH * NO) {                 // i = k*128 + o  ->  W2[o*NH + k]
        int k = i >> 7, o = i & (NO - 1);
        g_W2T[i] = W2[(size_t)o * NH + k];
    }
}

// ---------------- GEMM1 (split-K = 4, contiguous 512-chunks, serial combine) -----------
// cur1[m,n] = ((((0+p0)+p1)+p2)+p3) + b1[n], each p serial ascending-k FMA.
__global__ void __launch_bounds__(256) gemm1_kernel(const float* __restrict__ X,
                                                    const float* __restrict__ W1,
                                                    const float* __restrict__ b1) {
    __shared__ float As[8][128];   // [k][m]
    __shared__ float Bs[8][128];   // [k][n]
    const int tid = threadIdx.x;
    const int bm = blockIdx.y * 128;
    const int bn = blockIdx.x * 128;

    const int ldr = tid >> 1;            // 0..127
    const int ldc = (tid & 1) << 2;      // 0 or 4

    const float* Ap = X  + (size_t)(bm + ldr) * NI + ldc;
    const float* Bp = W1 + (size_t)(bn + ldr) * NI + ldc;

    const int tr = (tid >> 4) << 3;      // row base 0..120 step 8
    const int c0 = (tid & 15) << 2;      // col base (2nd group at +64)

    unsigned long long acc[8][4];        // current chunk partial
    unsigned long long tot[8][4];        // running serial-combined sum
#pragma unroll
    for (int i = 0; i < 8; i++)
#pragma unroll
        for (int j = 0; j < 4; j++) { acc[i][j] = 0ull; tot[i][j] = 0ull; }

    float4 av = *(const float4*)Ap;
    float4 bv = *(const float4*)Bp;

#pragma unroll 1
    for (int p = 0; p < 4; p++) {
#pragma unroll 1
        for (int k0 = p * 512; k0 < (p + 1) * 512; k0 += 8) {
            As[ldc + 0][ldr] = av.x;  As[ldc + 1][ldr] = av.y;
            As[ldc + 2][ldr] = av.z;  As[ldc + 3][ldr] = av.w;
            Bs[ldc + 0][ldr] = bv.x;  Bs[ldc + 1][ldr] = bv.y;
            Bs[ldc + 2][ldr] = bv.z;  Bs[ldc + 3][ldr] = bv.w;
            __syncthreads();
            if (k0 + 8 < NI) {
                av = *(const float4*)(Ap + k0 + 8);
                bv = *(const float4*)(Bp + k0 + 8);
            }
#pragma unroll
            for (int kk = 0; kk < 8; kk++) {
                float4 a0 = *(const float4*)&As[kk][tr];
                float4 a1 = *(const float4*)&As[kk][tr + 4];
                ulonglong2 w0 = *(const ulonglong2*)&Bs[kk][c0];
                ulonglong2 w1 = *(const ulonglong2*)&Bs[kk][c0 + 64];
                unsigned long long ad[8];
                ad[0] = dup2(a0.x); ad[1] = dup2(a0.y); ad[2] = dup2(a0.z); ad[3] = dup2(a0.w);
                ad[4] = dup2(a1.x); ad[5] = dup2(a1.y); ad[6] = dup2(a1.z); ad[7] = dup2(a1.w);
#pragma unroll
                for (int i = 0; i < 8; i++) {
                    ffma2(acc[i][0], ad[i], w0.x);
                    ffma2(acc[i][1], ad[i], w0.y);
                    ffma2(acc[i][2], ad[i], w1.x);
                    ffma2(acc[i][3], ad[i], w1.y);
                }
            }
            __syncthreads();
        }
        // serial ascending combine: tot += chunk_p
#pragma unroll
        for (int i = 0; i < 8; i++)
#pragma unroll
            for (int j = 0; j < 4; j++) { fadd2(tot[i][j], acc[i][j]); acc[i][j] = 0ull; }
    }

    float4 bias0 = *(const float4*)(b1 + bn + c0);
    float4 bias1 = *(const float4*)(b1 + bn + c0 + 64);
#pragma unroll
    for (int i = 0; i < 8; i++) {
        float2 p0 = unp(tot[i][0]);
        float2 p1 = unp(tot[i][1]);
        float2 p2 = unp(tot[i][2]);
        float2 p3 = unp(tot[i][3]);
        float* Crow = g_cur1 + (size_t)(bm + tr + i) * NH + bn;
        *(float4*)(Crow + c0) = make_float4(
            __fadd_rn(p0.x, bias0.x), __fadd_rn(p0.y, bias0.y),
            __fadd_rn(p1.x, bias0.z), __fadd_rn(p1.y, bias0.w));
        *(float4*)(Crow + c0 + 64) = make_float4(
            __fadd_rn(p2.x, bias1.x), __fadd_rn(p2.y, bias1.y),
            __fadd_rn(p3.x, bias1.z), __fadd_rn(p3.y, bias1.w));
    }
}

// ---------------- patch (same split4-512 serial semantics as bulk, consistency) --------
__global__ void patch_kernel(const float* __restrict__ X, const float* __restrict__ W1,
                             const float* __restrict__ b1) {
    int t = threadIdx.x;                             // 64 threads
    const float* xr = X + (size_t)t * BATCH * NI;    // row (t, b=0)
    float tot = 0.0f;
#pragma unroll 1
    for (int s = 0; s < 4; s++) {
        float acc = 0.0f;
        for (int k = s * 512; k < (s + 1) * 512; k++)
            acc = __fmaf_rn(xr[k], W1[k], acc);
        tot = __fadd_rn(tot, acc);
    }
    g_cur1[(size_t)(t * BATCH) * NH] = __fadd_rn(tot, b1[0]);
}

// ---------------- per-step layer-1 LIF update (CONTRACTED: m' = fma(0.9,m,c) - r) ------
// out layout: [0, 64*4096) spk1_trace | [.., +64) mem1_trace | [.., +64*256*128) spk2
__global__ void __launch_bounds__(256) update1_kernel(int t, float* __restrict__ out) {
    int i = blockIdx.x * blockDim.x + threadIdx.x;   // < BN
    float m = g_mem1[i];
    float r = (m > 1.0f) ? 1.0f : 0.0f;
    float c = __ldcs(&g_cur1[(size_t)t * BN + i]);
    m = __fsub_rn(__fmaf_rn(0.9f, m, c), r);
    float s = (m > 1.0f) ? 1.0f : 0.0f;
    g_mem1[i] = m;
    g_spk1[i] = s;
    if (i < NH) out[t * NH + i] = s;                 // spk1 of batch row 0
    if (i == 0) out[T_STEPS * NH + t] = m;           // mem1[0,0]
}

// ---------------- per-step layer-2: 512-chunk (S=8) serial dot + FMA-LIF ---------------
__global__ void __launch_bounds__(1024) layer2_kernel(int t, const float* __restrict__ b2,
                                                      float* __restrict__ out) {
    const int tid = threadIdx.x;
    const int b = blockIdx.x * 8 + (tid >> 7);       // 32 blocks x 8 batch rows
    const int o = tid & (NO - 1);

    const float* sp = g_spk1 + (size_t)b * NH;
    const float* wt = g_W2T + o;

    float tot = 0.0f;
#pragma unroll 1
    for (int s = 0; s < 8; s++) {
        float acc = 0.0f;
#pragma unroll 8
        for (int k = s * 512; k < (s + 1) * 512; k++)
            acc = __fmaf_rn(sp[k], wt[(size_t)k * NO], acc);
        tot = __fadd_rn(tot, acc);
    }
    float c = __fadd_rn(tot, b2[o]);

    int i = b * NO + o;
    float m = g_mem2[i];
    float r = (m > 1.0f) ? 1.0f : 0.0f;
    m = __fsub_rn(__fmaf_rn(0.8f, m, c), r);
    g_mem2[i] = m;
    out[(size_t)T_STEPS * NH + T_STEPS + (size_t)t * BO + i] = (m > 1.0f) ? 1.0f : 0.0f;
}

// ---------------- launch ----------------
extern "C" void kernel_launch(void* const* d_in, const int* in_sizes, int n_in,
                              void* d_out, int out_size) {
    const float* x  = (const float*)d_in[0];
    const float* W1 = (const float*)d_in[1];
    const float* b1 = (const float*)d_in[2];
    const float* W2 = (const float*)d_in[3];
    const float* b2 = (const float*)d_in[4];
    float* out = (float*)d_out;

    init_kernel<<<BN / 256, 256>>>(W2);
    gemm1_kernel<<<dim3(NH / 128, (T_STEPS * BATCH) / 128), 256>>>(x, W1, b1);
    patch_kernel<<<1, T_STEPS>>>(x, W1, b1);
    for (int t = 0; t < T_STEPS; t++) {
        update1_kernel<<<BN / 256, 256>>>(t, out);
        layer2_kernel<<<BATCH / 8, 1024>>>(t, b2, out);
    }
}

// round 11
// speedup vs baseline: 2.4118x; 2.4118x over previous
#include <cuda_runtime.h>
#include <cuda_bf16.h>

#define T_STEPS 64
#define BATCH   256
#define NI      2048
#define NH      4096
#define NO      128
#define BN      (BATCH * NH)      // 1048576
#define BO      (BATCH * NO)      // 32768

// ---------------- persistent device scratch (static: no runtime allocs) ----------------
__device__ float g_cur1[(size_t)T_STEPS * BN];   // 256 MiB: precomputed layer-1 currents
__device__ float g_mem1[BN];
__device__ float g_spk1[BN];
__device__ float g_mem2[BO];
__device__ float g_W2T[NH * NO];                 // W2 transposed: [k][o], 2 MiB
__device__ float g_cur2p[8 * BO];                // 8 chunk partials for layer 2 (1 MiB)

// ---------------- packed f32x2 helpers (per-lane IEEE rn rounding) ---------------------
__device__ __forceinline__ void ffma2(unsigned long long &d, unsigned long long a,
                                      unsigned long long b) {
    asm("fma.rn.f32x2 %0, %1, %2, %0;" : "+l"(d) : "l"(a), "l"(b));
}
__device__ __forceinline__ unsigned long long dup2(float x) {
    unsigned long long r;
    asm("mov.b64 %0, {%1, %1};" : "=l"(r) : "f"(x));
    return r;
}
__device__ __forceinline__ float2 unp(unsigned long long v) {
    float2 r;
    asm("mov.b64 {%0, %1}, %2;" : "=f"(r.x), "=f"(r.y) : "l"(v));
    return r;
}

// ---------------- init: zero recurrent state + transpose W2 ---------------------------
__global__ void init_kernel(const float* __restrict__ W2) {
    int i = blockIdx.x * blockDim.x + threadIdx.x;
    if (i < BN) g_mem1[i] = 0.0f;
    if (i < BO) g_mem2[i] = 0.0f;
    if (i < NH * NO) {                 // i = k*128 + o  ->  W2[o*NH + k]
        int k = i >> 7, o = i & (NO - 1);
        g_W2T[i] = W2[(size_t)o * NH + k];
    }
}

// ---------------- GEMM1 (split-K=4, 512-chunks, serial combine — combine via gmem RMW) -
// Per element, EXACT R10 order: p0 written; then tot=fadd(tot,p1); fadd(tot,p2);
// then fadd(fadd(tot,p3), bias). Same thread owns the element across all chunks.
__global__ void __launch_bounds__(256, 2) gemm1_kernel(const float* __restrict__ X,
                                                       const float* __restrict__ W1,
                                                       const float* __restrict__ b1) {
    __shared__ float As[8][128];   // [k][m]
    __shared__ float Bs[8][128];   // [k][n]
    const int tid = threadIdx.x;
    const int bm = blockIdx.y * 128;
    const int bn = blockIdx.x * 128;

    const int ldr = tid >> 1;            // 0..127
    const int ldc = (tid & 1) << 2;      // 0 or 4

    const float* Ap = X  + (size_t)(bm + ldr) * NI + ldc;
    const float* Bp = W1 + (size_t)(bn + ldr) * NI + ldc;

    const int tr = (tid >> 4) << 3;      // row base 0..120 step 8
    const int c0 = (tid & 15) << 2;      // col base (2nd group at +64)

    unsigned long long acc[8][4];        // current chunk partial only (64 regs)

    float4 av = *(const float4*)Ap;
    float4 bv = *(const float4*)Bp;

#pragma unroll 1
    for (int p = 0; p < 4; p++) {
#pragma unroll
        for (int i = 0; i < 8; i++)
#pragma unroll
            for (int j = 0; j < 4; j++) acc[i][j] = 0ull;

#pragma unroll 1
        for (int k0 = p * 512; k0 < (p + 1) * 512; k0 += 8) {
            As[ldc + 0][ldr] = av.x;  As[ldc + 1][ldr] = av.y;
            As[ldc + 2][ldr] = av.z;  As[ldc + 3][ldr] = av.w;
            Bs[ldc + 0][ldr] = bv.x;  Bs[ldc + 1][ldr] = bv.y;
            Bs[ldc + 2][ldr] = bv.z;  Bs[ldc + 3][ldr] = bv.w;
            __syncthreads();
            if (k0 + 8 < NI) {
                av = *(const float4*)(Ap + k0 + 8);
                bv = *(const float4*)(Bp + k0 + 8);
            }
#pragma unroll
            for (int kk = 0; kk < 8; kk++) {
                float4 a0 = *(const float4*)&As[kk][tr];
                float4 a1 = *(const float4*)&As[kk][tr + 4];
                ulonglong2 w0 = *(const ulonglong2*)&Bs[kk][c0];
                ulonglong2 w1 = *(const ulonglong2*)&Bs[kk][c0 + 64];
                unsigned long long ad[8];
                ad[0] = dup2(a0.x); ad[1] = dup2(a0.y); ad[2] = dup2(a0.z); ad[3] = dup2(a0.w);
                ad[4] = dup2(a1.x); ad[5] = dup2(a1.y); ad[6] = dup2(a1.z); ad[7] = dup2(a1.w);
#pragma unroll
                for (int i = 0; i < 8; i++) {
                    ffma2(acc[i][0], ad[i], w0.x);
                    ffma2(acc[i][1], ad[i], w0.y);
                    ffma2(acc[i][2], ad[i], w1.x);
                    ffma2(acc[i][3], ad[i], w1.y);
                }
            }
            __syncthreads();
        }

        // merge this chunk's partial into g_cur1 (serial ascending combine)
#pragma unroll
        for (int i = 0; i < 8; i++) {
            float2 q0 = unp(acc[i][0]);
            float2 q1 = unp(acc[i][1]);
            float2 q2 = unp(acc[i][2]);
            float2 q3 = unp(acc[i][3]);
            float* Crow = g_cur1 + (size_t)(bm + tr + i) * NH + bn;
            float4 lo = make_float4(q0.x, q0.y, q1.x, q1.y);
            float4 hi = make_float4(q2.x, q2.y, q3.x, q3.y);
            if (p == 0) {
                *(float4*)(Crow + c0)      = lo;
                *(float4*)(Crow + c0 + 64) = hi;
            } else if (p < 3) {
                float4 t0 = *(const float4*)(Crow + c0);
                float4 t1 = *(const float4*)(Crow + c0 + 64);
                t0.x = __fadd_rn(t0.x, lo.x); t0.y = __fadd_rn(t0.y, lo.y);
                t0.z = __fadd_rn(t0.z, lo.z); t0.w = __fadd_rn(t0.w, lo.w);
                t1.x = __fadd_rn(t1.x, hi.x); t1.y = __fadd_rn(t1.y, hi.y);
                t1.z = __fadd_rn(t1.z, hi.z); t1.w = __fadd_rn(t1.w, hi.w);
                *(float4*)(Crow + c0)      = t0;
                *(float4*)(Crow + c0 + 64) = t1;
            } else {
                float4 bias0 = *(const float4*)(b1 + bn + c0);
                float4 bias1 = *(const float4*)(b1 + bn + c0 + 64);
                float4 t0 = *(const float4*)(Crow + c0);
                float4 t1 = *(const float4*)(Crow + c0 + 64);
                t0.x = __fadd_rn(__fadd_rn(t0.x, lo.x), bias0.x);
                t0.y = __fadd_rn(__fadd_rn(t0.y, lo.y), bias0.y);
                t0.z = __fadd_rn(__fadd_rn(t0.z, lo.z), bias0.z);
                t0.w = __fadd_rn(__fadd_rn(t0.w, lo.w), bias0.w);
                t1.x = __fadd_rn(__fadd_rn(t1.x, hi.x), bias1.x);
                t1.y = __fadd_rn(__fadd_rn(t1.y, hi.y), bias1.y);
                t1.z = __fadd_rn(__fadd_rn(t1.z, hi.z), bias1.z);
                t1.w = __fadd_rn(__fadd_rn(t1.w, hi.w), bias1.w);
                *(float4*)(Crow + c0)      = t0;
                *(float4*)(Crow + c0 + 64) = t1;
            }
        }
    }
}

// ---------------- patch (split4-512 serial, element (0,0) — unchanged anchor) ----------
__global__ void patch_kernel(const float* __restrict__ X, const float* __restrict__ W1,
                             const float* __restrict__ b1) {
    int t = threadIdx.x;                             // 64 threads
    const float* xr = X + (size_t)t * BATCH * NI;    // row (t, b=0)
    float tot = 0.0f;
#pragma unroll 1
    for (int s = 0; s < 4; s++) {
        float acc = 0.0f;
        for (int k = s * 512; k < (s + 1) * 512; k++)
            acc = __fmaf_rn(xr[k], W1[k], acc);
        tot = __fadd_rn(tot, acc);
    }
    g_cur1[(size_t)(t * BATCH) * NH] = __fadd_rn(tot, b1[0]);
}

// ---------------- per-step layer-1 LIF (float4, contracted fma form) -------------------
// out layout: [0, 64*4096) spk1_trace | [.., +64) mem1_trace | [.., +64*256*128) spk2
__global__ void __launch_bounds__(256) update1_kernel(int t, float* __restrict__ out) {
    int v = blockIdx.x * blockDim.x + threadIdx.x;   // < BN/4, grid 1024
    float4 m4 = ((const float4*)g_mem1)[v];
    float4 c4 = __ldcs(&((const float4*)(g_cur1 + (size_t)t * BN))[v]);
    float4 s4;
    {
        float r = (m4.x > 1.0f) ? 1.0f : 0.0f;
        m4.x = __fsub_rn(__fmaf_rn(0.9f, m4.x, c4.x), r);
        s4.x = (m4.x > 1.0f) ? 1.0f : 0.0f;
    }
    {
        float r = (m4.y > 1.0f) ? 1.0f : 0.0f;
        m4.y = __fsub_rn(__fmaf_rn(0.9f, m4.y, c4.y), r);
        s4.y = (m4.y > 1.0f) ? 1.0f : 0.0f;
    }
    {
        float r = (m4.z > 1.0f) ? 1.0f : 0.0f;
        m4.z = __fsub_rn(__fmaf_rn(0.9f, m4.z, c4.z), r);
        s4.z = (m4.z > 1.0f) ? 1.0f : 0.0f;
    }
    {
        float r = (m4.w > 1.0f) ? 1.0f : 0.0f;
        m4.w = __fsub_rn(__fmaf_rn(0.9f, m4.w, c4.w), r);
        s4.w = (m4.w > 1.0f) ? 1.0f : 0.0f;
    }
    ((float4*)g_mem1)[v] = m4;
    ((float4*)g_spk1)[v] = s4;
    if (v < NH / 4) ((float4*)(out + (size_t)t * NH))[v] = s4;   // spk1 of batch row 0
    if (v == 0) out[T_STEPS * NH + t] = m4.x;                    // mem1[0,0]
}

// ---------------- per-step layer-2 chunk partials (one 512-chunk per block) ------------
// grid (8 chunks, 8 b-groups); block 1024 = 32 b-rows x 32 lanes (4 o each).
// Within chunk: serial ascending-k FMA per output element (exact R10 chunk order).
__global__ void __launch_bounds__(1024) layer2_kernel() {
    __shared__ float sp_s[32][64];     // [b][k-sub]  8 KB
    __shared__ float wt_s[64][128];    // [k-sub][o] 32 KB
    const int s  = blockIdx.x;         // chunk 0..7
    const int b0 = blockIdx.y * 32;    // batch group
    const int tid = threadIdx.x;
    const int wid = tid >> 5;          // b row 0..31
    const int lane = tid & 31;         // o/4
    const int k0 = s * 512;

    unsigned long long acc0 = 0ull, acc1 = 0ull;

#pragma unroll 1
    for (int sub = 0; sub < 8; sub++) {
        __syncthreads();
        // stage spike subtile: 32b x 64k
        if (tid < 512) {
            int bb = tid >> 4, kq = tid & 15;
            *(float4*)&sp_s[bb][kq * 4] =
                *(const float4*)&g_spk1[(size_t)(b0 + bb) * NH + k0 + sub * 64 + kq * 4];
        }
        // stage weight subtile: 64k x 128o
        {
            int idx = tid;             // 2048 float4 loads, 2 per thread
#pragma unroll
            for (int rep = 0; rep < 2; rep++, idx += 1024) {
                int kk = idx >> 5, oq = idx & 31;
                *(float4*)&wt_s[kk][oq * 4] =
                    *(const float4*)&g_W2T[(size_t)(k0 + sub * 64 + kk) * NO + oq * 4];
            }
        }
        __syncthreads();
#pragma unroll
        for (int kk = 0; kk < 64; kk++) {
            unsigned long long a = dup2(sp_s[wid][kk]);
            ulonglong2 w = *(const ulonglong2*)&wt_s[kk][lane * 4];
            ffma2(acc0, a, w.x);
            ffma2(acc1, a, w.y);
        }
    }

    float2 q0 = unp(acc0), q1 = unp(acc1);
    float* dst = g_cur2p + (size_t)s * BO + (size_t)(b0 + wid) * NO + lane * 4;
    *(float4*)dst = make_float4(q0.x, q0.y, q1.x, q1.y);
}

// ---------------- per-step layer-2 combine + LIF: serial ascending chunks + bias -------
__global__ void __launch_bounds__(256) update2_kernel(int t, const float* __restrict__ b2,
                                                      float* __restrict__ out) {
    int v = blockIdx.x * blockDim.x + threadIdx.x;   // < BO/4, grid 32
    float4 tot = make_float4(0.0f, 0.0f, 0.0f, 0.0f);
#pragma unroll
    for (int s = 0; s < 8; s++) {
        float4 p = ((const float4*)(g_cur2p + (size_t)s * BO))[v];
        tot.x = __fadd_rn(tot.x, p.x);
        tot.y = __fadd_rn(tot.y, p.y);
        tot.z = __fadd_rn(tot.z, p.z);
        tot.w = __fadd_rn(tot.w, p.w);
    }
    float4 bb = ((const float4*)b2)[v & 31];
    float4 m4 = ((const float4*)g_mem2)[v];
    float4 s4;
    {
        float c = __fadd_rn(tot.x, bb.x);
        float r = (m4.x > 1.0f) ? 1.0f : 0.0f;
        m4.x = __fsub_rn(__fmaf_rn(0.8f, m4.x, c), r);
        s4.x = (m4.x > 1.0f) ? 1.0f : 0.0f;
    }
    {
        float c = __fadd_rn(tot.y, bb.y);
        float r = (m4.y > 1.0f) ? 1.0f : 0.0f;
        m4.y = __fsub_rn(__fmaf_rn(0.8f, m4.y, c), r);
        s4.y = (m4.y > 1.0f) ? 1.0f : 0.0f;
    }
    {
        float c = __fadd_rn(tot.z, bb.z);
        float r = (m4.z > 1.0f) ? 1.0f : 0.0f;
        m4.z = __fsub_rn(__fmaf_rn(0.8f, m4.z, c), r);
        s4.z = (m4.z > 1.0f) ? 1.0f : 0.0f;
    }
    {
        float c = __fadd_rn(tot.w, bb.w);
        float r = (m4.w > 1.0f) ? 1.0f : 0.0f;
        m4.w = __fsub_rn(__fmaf_rn(0.8f, m4.w, c), r);
        s4.w = (m4.w > 1.0f) ? 1.0f : 0.0f;
    }
    ((float4*)g_mem2)[v] = m4;
    ((float4*)(out + (size_t)T_STEPS * NH + T_STEPS + (size_t)t * BO))[v] = s4;
}

// ---------------- launch ----------------
extern "C" void kernel_launch(void* const* d_in, const int* in_sizes, int n_in,
                              void* d_out, int out_size) {
    const float* x  = (const float*)d_in[0];
    const float* W1 = (const float*)d_in[1];
    const float* b1 = (const float*)d_in[2];
    const float* W2 = (const float*)d_in[3];
    const float* b2 = (const float*)d_in[4];
    float* out = (float*)d_out;

    init_kernel<<<BN / 256, 256>>>(W2);
    gemm1_kernel<<<dim3(NH / 128, (T_STEPS * BATCH) / 128), 256>>>(x, W1, b1);
    patch_kernel<<<1, T_STEPS>>>(x, W1, b1);
    for (int t = 0; t < T_STEPS; t++) {
        update1_kernel<<<BN / 1024, 256>>>(t, out);
        layer2_kernel<<<dim3(8, BATCH / 32), 1024>>>();
        update2_kernel<<<BO / 1024, 256>>>(t, b2, out);
    }
}